// round 1
// baseline (speedup 1.0000x reference)
#include <cuda_runtime.h>
#include <cstdint>

#define S_LEN 4096
#define BATCH 4
#define V_DIM 64
#define D_DIM 128

// ---------------------------------------------------------------------------
// Pre-transposed weights, [j][i] layout so that warp lanes (consecutive i)
// read consecutive addresses (coalesced LDG / conflict-free LDS patterns).
// ---------------------------------------------------------------------------
__device__ float g_cPt[64 * 64];     // char_P^T : [j][i], j<64, i<64
__device__ float g_M1t[64 * 128];    // M1^T     : [j][i], j<64, i<128
__device__ float g_R1t[64 * 128];    // R1^T
__device__ float g_M2t[128 * 128];   // M2^T     : [j][i], j<128, i<128
__device__ float g_P1t[128 * 128];   // P1^T
__device__ float g_P2t[128 * 128];   // P2^T

__global__ void transpose_weights_kernel(
    const float* __restrict__ cP, const float* __restrict__ M1,
    const float* __restrict__ R1, const float* __restrict__ M2,
    const float* __restrict__ P1, const float* __restrict__ P2)
{
    int t = blockIdx.x * blockDim.x + threadIdx.x;
    if (t < 16384) {
        int i = t >> 7, j = t & 127;
        g_M2t[j * 128 + i] = M2[t];
        g_P1t[j * 128 + i] = P1[t];
        g_P2t[j * 128 + i] = P2[t];
    }
    if (t < 8192) {
        int i = t >> 6, j = t & 63;
        g_M1t[j * 128 + i] = M1[t];
        g_R1t[j * 128 + i] = R1[t];
    }
    if (t < 4096) {
        int i = t >> 6, j = t & 63;
        g_cPt[j * 64 + i] = cP[t];
    }
}

// ---------------------------------------------------------------------------
// phase(s, p) = cos(2*pi*s / p), matching the reference's float expression.
// Argument built the same way (2pi*s then /p), then Cody-Waite reduction to
// [-pi, pi] and __cosf (abs err ~2^-21 there). n <= 2048 so fmaf terms exact.
// ---------------------------------------------------------------------------
__device__ __forceinline__ float phase_cos(float sf, float pf)
{
    float x = __fdividef(6.28318530717958647692f * sf, pf);
    float n = rintf(x * 0.15915494309189533577f);          // x / (2*pi), rounded
    float r = fmaf(n, -6.28318548202514648438f, x);        // x - n*hi (hi = fl(2pi))
    r = fmaf(n, 1.74845560007e-7f, r);                     // - n*lo (lo = 2pi - hi)
    return __cosf(r);
}

__device__ __forceinline__ float warpsum(float v)
{
#pragma unroll
    for (int o = 16; o > 0; o >>= 1) v += __shfl_xor_sync(0xffffffffu, v, o);
    return v;
}

// Shared-memory layout (floats):
//  phiD : 16384  [j][i] 128x128
//  phiV :  4096  [j][i] 64x64
//  xs   :   256  [b][j]
//  hs   :   256  [b][j]
//  t1s  :   512  [b][i]
//  ln1  :   512
//  h1s  :   512
//  t2s  :   512
//  ln2  :   512
//  mu   :     4
//  rs   :     4
#define SM_FLOATS 23560
#define SMEM_BYTES (SM_FLOATS * 4)

__global__ __launch_bounds__(256, 2)
void hier_kernel(const int*   __restrict__ tokens,
                 const int*   __restrict__ positions,
                 const float* __restrict__ emb,
                 const float* __restrict__ g1, const float* __restrict__ b1,
                 const float* __restrict__ g2, const float* __restrict__ b2,
                 float*       __restrict__ out)
{
    extern __shared__ float sm[];
    float* phiD = sm;               // 16384
    float* phiV = sm + 16384;       //  4096
    float* xs   = sm + 20480;       //   256
    float* hs   = sm + 20736;       //   256
    float* t1s  = sm + 20992;       //   512
    float* ln1  = sm + 21504;       //   512
    float* h1s  = sm + 22016;       //   512
    float* t2s  = sm + 22528;       //   512
    float* ln2  = sm + 23040;       //   512
    float* mu   = sm + 23552;       //     4
    float* rs   = sm + 23556;       //     4

    const int tid = threadIdx.x;
    const int s   = blockIdx.x;
    const float sf = (float)positions[s];

    // ---- phase tables (stored transposed: entry k -> i = k&(d-1) fastest) ----
#pragma unroll 4
    for (int k = tid; k < 16384; k += 256) {
        int i = k & 127, j = k >> 7;
        phiD[k] = phase_cos(sf, (float)(i * 128 + j + 2));
    }
#pragma unroll 2
    for (int k = tid; k < 4096; k += 256) {
        int i = k & 63, j = k >> 6;
        phiV[k] = phase_cos(sf, (float)(i * 64 + j + 2));
    }

    // ---- gather embeddings: xs[b][j] ----
    {
        int b = tid >> 6, j = tid & 63;
        int tok = tokens[b * S_LEN + s];
        xs[tid] = emb[tok * V_DIM + j];
    }
    __syncthreads();

    // mapping A: b = tid>>6 in [0,4), iv = tid&63
    const int b  = tid >> 6;
    const int iv = tid & 63;

    // ---- layer 0: h[b][i] = sum_j char_P[i][j]*phiV(i,j)*x[b][j] ----
    {
        float acc = 0.f;
        const float* xb = xs + b * 64;
#pragma unroll 8
        for (int j = 0; j < 64; ++j) {
            float pf = __ldg(&g_cPt[j * 64 + iv]) * phiV[j * 64 + iv];
            acc = fmaf(pf, xb[j], acc);
        }
        hs[b * 64 + iv] = acc;
    }
    __syncthreads();

    // ---- t1 = M1 @ h   (each thread: rows iv, iv+64 for its b) ----
    float a0 = 0.f, a1 = 0.f;
    {
        const float* hb = hs + b * 64;
#pragma unroll 8
        for (int j = 0; j < 64; ++j) {
            float hv = hb[j];
            a0 = fmaf(__ldg(&g_M1t[j * 128 + iv]),      hv, a0);
            a1 = fmaf(__ldg(&g_M1t[j * 128 + iv + 64]), hv, a1);
        }
        t1s[b * 128 + iv]      = a0;
        t1s[b * 128 + iv + 64] = a1;
    }
    __syncthreads();

    // ---- layernorm 1 stats ----
    if (tid < 128) {
        int bb = tid >> 5, l = tid & 31;
        const float* tb = t1s + bb * 128;
        float v0 = tb[l], v1 = tb[l + 32], v2 = tb[l + 64], v3 = tb[l + 96];
        float mean = warpsum(v0 + v1 + v2 + v3) * 0.0078125f;
        float d0 = v0 - mean, d1 = v1 - mean, d2 = v2 - mean, d3 = v3 - mean;
        float var = warpsum(d0 * d0 + d1 * d1 + d2 * d2 + d3 * d3) * 0.0078125f;
        if (l == 0) { mu[bb] = mean; rs[bb] = rsqrtf(var + 1e-5f); }
    }
    __syncthreads();
    {
        float m = mu[b], r = rs[b];
        ln1[b * 128 + iv]      = (a0 - m) * r * __ldg(&g1[iv])      + __ldg(&b1[iv]);
        ln1[b * 128 + iv + 64] = (a1 - m) * r * __ldg(&g1[iv + 64]) + __ldg(&b1[iv + 64]);
    }
    __syncthreads();

    // mapping B: i2 = tid&127, batch pair b0 = 2*(tid>>7)
    const int i2 = tid & 127;
    const int b0 = (tid >> 7) << 1;

    // ---- h1 = posnk(ln1, P1, phiD) + R1 @ h  (P*phi shared across b-pair) ----
    {
        float c0 = 0.f, c1 = 0.f;
        const float* lA = ln1 + b0 * 128;
        const float* lB = lA + 128;
#pragma unroll 8
        for (int j = 0; j < 128; ++j) {
            float pf = __ldg(&g_P1t[j * 128 + i2]) * phiD[j * 128 + i2];
            c0 = fmaf(pf, lA[j], c0);
            c1 = fmaf(pf, lB[j], c1);
        }
        const float* hA = hs + b0 * 64;
        const float* hB = hA + 64;
#pragma unroll 8
        for (int j = 0; j < 64; ++j) {
            float rv = __ldg(&g_R1t[j * 128 + i2]);
            c0 = fmaf(rv, hA[j], c0);
            c1 = fmaf(rv, hB[j], c1);
        }
        h1s[b0 * 128 + i2]       = c0;
        h1s[b0 * 128 + 128 + i2] = c1;
    }
    __syncthreads();

    // ---- t2 = M2 @ h1 ----
    float e0 = 0.f, e1 = 0.f;
    {
        const float* hb = h1s + b * 128;
#pragma unroll 8
        for (int j = 0; j < 128; ++j) {
            float hv = hb[j];
            e0 = fmaf(__ldg(&g_M2t[j * 128 + iv]),      hv, e0);
            e1 = fmaf(__ldg(&g_M2t[j * 128 + iv + 64]), hv, e1);
        }
        t2s[b * 128 + iv]      = e0;
        t2s[b * 128 + iv + 64] = e1;
    }
    __syncthreads();

    // ---- layernorm 2 stats ----
    if (tid < 128) {
        int bb = tid >> 5, l = tid & 31;
        const float* tb = t2s + bb * 128;
        float v0 = tb[l], v1 = tb[l + 32], v2 = tb[l + 64], v3 = tb[l + 96];
        float mean = warpsum(v0 + v1 + v2 + v3) * 0.0078125f;
        float d0 = v0 - mean, d1 = v1 - mean, d2 = v2 - mean, d3 = v3 - mean;
        float var = warpsum(d0 * d0 + d1 * d1 + d2 * d2 + d3 * d3) * 0.0078125f;
        if (l == 0) { mu[bb] = mean; rs[bb] = rsqrtf(var + 1e-5f); }
    }
    __syncthreads();
    {
        float m = mu[b], r = rs[b];
        ln2[b * 128 + iv]      = (e0 - m) * r * __ldg(&g2[iv])      + __ldg(&b2[iv]);
        ln2[b * 128 + iv + 64] = (e1 - m) * r * __ldg(&g2[iv + 64]) + __ldg(&b2[iv + 64]);
    }
    __syncthreads();

    // ---- out = posnk(ln2, P2, phiD) + t2 ----
    {
        float o0 = t2s[b0 * 128 + i2];
        float o1 = t2s[b0 * 128 + 128 + i2];
        const float* lA = ln2 + b0 * 128;
        const float* lB = lA + 128;
#pragma unroll 8
        for (int j = 0; j < 128; ++j) {
            float pf = __ldg(&g_P2t[j * 128 + i2]) * phiD[j * 128 + i2];
            o0 = fmaf(pf, lA[j], o0);
            o1 = fmaf(pf, lB[j], o1);
        }
        out[((size_t)b0 * S_LEN + s) * 128 + i2]       = o0;
        out[((size_t)(b0 + 1) * S_LEN + s) * 128 + i2] = o1;
    }
}

extern "C" void kernel_launch(void* const* d_in, const int* in_sizes, int n_in,
                              void* d_out, int out_size)
{
    const int*   tokens    = (const int*)  d_in[0];
    const int*   positions = (const int*)  d_in[1];
    const float* emb       = (const float*)d_in[2];
    const float* char_P    = (const float*)d_in[3];
    const float* M1        = (const float*)d_in[4];
    const float* P1        = (const float*)d_in[5];
    const float* g1        = (const float*)d_in[6];
    const float* b1        = (const float*)d_in[7];
    const float* R1        = (const float*)d_in[8];
    const float* M2        = (const float*)d_in[9];
    const float* P2        = (const float*)d_in[10];
    const float* g2        = (const float*)d_in[11];
    const float* b2        = (const float*)d_in[12];
    float* out = (float*)d_out;

    // idempotent, deterministic attribute set (needed for 94 KB dynamic smem)
    cudaFuncSetAttribute(hier_kernel,
                         cudaFuncAttributeMaxDynamicSharedMemorySize, SMEM_BYTES);

    transpose_weights_kernel<<<64, 256>>>(char_P, M1, R1, M2, P1, P2);
    hier_kernel<<<S_LEN, 256, SMEM_BYTES>>>(tokens, positions, emb,
                                            g1, b1, g2, b2, out);
}